// round 1
// baseline (speedup 1.0000x reference)
#include <cuda_runtime.h>
#include <cstdint>

#define B_ 8192
#define T_ 512
#define F_ 24
#define H_ 12

typedef unsigned long long u64;

// ---- f32x2 packed helpers (sm_103a; FFMA2 only reachable via PTX) ----
__device__ __forceinline__ u64 pk2(float lo, float hi) {
    u64 r; asm("mov.b64 %0,{%1,%2};" : "=l"(r) : "f"(lo), "f"(hi)); return r;
}
__device__ __forceinline__ u64 dup2(float v) {
    u64 r; asm("mov.b64 %0,{%1,%1};" : "=l"(r) : "f"(v)); return r;
}
__device__ __forceinline__ void fma2(u64 &d, u64 a, u64 b) {
    asm("fma.rn.f32x2 %0,%1,%2,%0;" : "+l"(d) : "l"(a), "l"(b));
}
__device__ __forceinline__ void unpk2(u64 v, float &lo, float &hi) {
    asm("mov.b64 {%0,%1},%2;" : "=f"(lo), "=f"(hi) : "l"(v));
}

// Accurate-enough tanh: 1 - 2/(e^{2x}+1). __expf -> MUFU.EX2, __fdividef -> MUFU.RCP.
// Handles saturation correctly (e=inf -> 1, e=0 -> -1). abs err ~1e-7.
__device__ __forceinline__ float fast_tanh(float x) {
    float e = __expf(x + x);
    return 1.0f - __fdividef(2.0f, e + 1.0f);
}

// 4 threads per batch element:
//   lane%4 = 2*ph + pf
//   ph: which 6 hidden units this thread accumulates (h in [6*ph, 6*ph+6))
//   pf: which input/recurrent half it sums over (f in [12*pf,..), k in [6*pf,..))
// Per step: 36 FFMA2 (input partial) + 18 FFMA2 (recurrent partial),
// shfl.xor(1) reduction across f-partners, 6 tanh, 6-shfl h broadcast.
__global__ void __launch_bounds__(128, 2)
rnn_fused_kernel(const float* __restrict__ x,
                 const float* __restrict__ W_ih, const float* __restrict__ b_ih,
                 const float* __restrict__ W_hh, const float* __restrict__ b_hh,
                 const float* __restrict__ W1,  const float* __restrict__ b1,
                 const float* __restrict__ W2,  const float* __restrict__ b2,
                 const float* __restrict__ W3,  const float* __restrict__ b3,
                 float* __restrict__ out)
{
    const int tid  = blockIdx.x * blockDim.x + threadIdx.x;
    const int elem = tid >> 2;
    const int lane = threadIdx.x & 31;
    const int pf   = lane & 1;
    const int ph   = (lane >> 1) & 1;
    const int h0   = ph * 6;
    const int f0   = pf * 12;
    const int k0   = pf * 6;
    const unsigned FULL = 0xFFFFFFFFu;

    // ---- load weights into registers (once), packed along h-pairs ----
    u64 Wihp[3][12];   // [h-pair][local f]
    u64 Whhp[3][6];    // [h-pair][local k]
    u64 binit[3];
    #pragma unroll
    for (int hp = 0; hp < 3; hp++) {
        const int ha = h0 + 2 * hp, hb = ha + 1;
        #pragma unroll
        for (int f = 0; f < 12; f++)
            Wihp[hp][f] = pk2(W_ih[ha * F_ + f0 + f], W_ih[hb * F_ + f0 + f]);
        #pragma unroll
        for (int k = 0; k < 6; k++)
            Whhp[hp][k] = pk2(W_hh[ha * H_ + k0 + k], W_hh[hb * H_ + k0 + k]);
        // bias contributed only by the pf==0 partial (avoid double count)
        binit[hp] = pf ? pk2(0.0f, 0.0f)
                       : pk2(b_ih[ha] + b_hh[ha], b_ih[hb] + b_hh[hb]);
    }

    const float* xb = x + (size_t)elem * (T_ * F_) + f0;

    // current-step x (12 floats = 3 float4), prefetched
    float4 xc0 = *(const float4*)(xb + 0);
    float4 xc1 = *(const float4*)(xb + 4);
    float4 xc2 = *(const float4*)(xb + 8);

    float h[6];      // h[k0 .. k0+5] (what recurrence needs)
    #pragma unroll
    for (int i = 0; i < 6; i++) h[i] = 0.0f;
    float hown[6];   // h[h0 .. h0+5] (what this thread computes)

    const int bcsrc = (lane & ~3) | (pf << 1);  // a lane whose ph == my pf

    for (int t = 0; t < T_; t++) {
        // prefetch next step's x (clamped at the end; overlaps the serial tail)
        const int tn = (t < T_ - 1) ? t + 1 : t;
        const float* xn = xb + (size_t)tn * F_;
        float4 n0 = *(const float4*)(xn + 0);
        float4 n1 = *(const float4*)(xn + 4);
        float4 n2 = *(const float4*)(xn + 8);

        u64 acc0 = binit[0], acc1 = binit[1], acc2 = binit[2];

        const float xs[12] = {xc0.x, xc0.y, xc0.z, xc0.w,
                              xc1.x, xc1.y, xc1.z, xc1.w,
                              xc2.x, xc2.y, xc2.z, xc2.w};
        #pragma unroll
        for (int f = 0; f < 12; f++) {
            u64 xd = dup2(xs[f]);
            fma2(acc0, Wihp[0][f], xd);
            fma2(acc1, Wihp[1][f], xd);
            fma2(acc2, Wihp[2][f], xd);
        }
        #pragma unroll
        for (int k = 0; k < 6; k++) {
            u64 hd = dup2(h[k]);
            fma2(acc0, Whhp[0][k], hd);
            fma2(acc1, Whhp[1][k], hd);
            fma2(acc2, Whhp[2][k], hd);
        }

        // reduce partial sums across the f-partner (lane ^ 1)
        float a0, a1, a2, a3, a4, a5;
        unpk2(acc0, a0, a1);
        unpk2(acc1, a2, a3);
        unpk2(acc2, a4, a5);
        a0 += __shfl_xor_sync(FULL, a0, 1);
        a1 += __shfl_xor_sync(FULL, a1, 1);
        a2 += __shfl_xor_sync(FULL, a2, 1);
        a3 += __shfl_xor_sync(FULL, a3, 1);
        a4 += __shfl_xor_sync(FULL, a4, 1);
        a5 += __shfl_xor_sync(FULL, a5, 1);

        hown[0] = fast_tanh(a0);
        hown[1] = fast_tanh(a1);
        hown[2] = fast_tanh(a2);
        hown[3] = fast_tanh(a3);
        hown[4] = fast_tanh(a4);
        hown[5] = fast_tanh(a5);

        // broadcast: fetch the h-half my recurrence slice needs
        #pragma unroll
        for (int i = 0; i < 6; i++)
            h[i] = __shfl_sync(FULL, hown[i], bcsrc);

        xc0 = n0; xc1 = n1; xc2 = n2;
    }

    // ---- gather full h_T and run the tiny MLP head ----
    float hf[12];
    const int base = lane & ~3;
    #pragma unroll
    for (int i = 0; i < 6; i++) {
        hf[i]     = __shfl_sync(FULL, hown[i], base);      // ph=0 lane: h[0:6]
        hf[6 + i] = __shfl_sync(FULL, hown[i], base + 2);  // ph=1 lane: h[6:12]
    }

    if ((lane & 3) == 0) {
        float o1[12];
        #pragma unroll
        for (int i = 0; i < 12; i++) {
            float s = b1[i];
            #pragma unroll
            for (int j = 0; j < 12; j++) s = fmaf(W1[i * 12 + j], hf[j], s);
            o1[i] = fmaxf(s, 0.0f);
        }
        float o2[12];
        #pragma unroll
        for (int i = 0; i < 12; i++) {
            float s = b2[i];
            #pragma unroll
            for (int j = 0; j < 12; j++) s = fmaf(W2[i * 12 + j], o1[j], s);
            o2[i] = fmaxf(s, 0.0f);
        }
        float s = b3[0];
        #pragma unroll
        for (int j = 0; j < 12; j++) s = fmaf(W3[j], o2[j], s);
        out[elem] = s;
    }
}

extern "C" void kernel_launch(void* const* d_in, const int* in_sizes, int n_in,
                              void* d_out, int out_size)
{
    (void)in_sizes; (void)n_in; (void)out_size;
    const float* x    = (const float*)d_in[0];
    const float* W_ih = (const float*)d_in[1];
    const float* b_ih = (const float*)d_in[2];
    const float* W_hh = (const float*)d_in[3];
    const float* b_hh = (const float*)d_in[4];
    const float* W1   = (const float*)d_in[5];
    const float* b1   = (const float*)d_in[6];
    const float* W2   = (const float*)d_in[7];
    const float* b2   = (const float*)d_in[8];
    const float* W3   = (const float*)d_in[9];
    const float* b3   = (const float*)d_in[10];
    float* out = (float*)d_out;

    // 4 threads/element * 8192 elements = 32768 threads
    rnn_fused_kernel<<<256, 128>>>(x, W_ih, b_ih, W_hh, b_hh,
                                   W1, b1, W2, b2, W3, b3, out);
}